// round 10
// baseline (speedup 1.0000x reference)
#include <cuda_runtime.h>
#include <cstdint>

// ReadingLayerReLU via mma.sync.m16n8k8 tf32 + ldmatrix + cp.async, BK=32.
// 128x128 block tile, 256 threads (8 warps, 4x2, 32x64 warp tile), 2-stage
// double buffer, 2 CTAs/SM (16 warps). fp32 staged raw; tf32 RNA cvt applied
// to fragment registers post-ldmatrix.
// key = relu(x @ W^T)        : M=16384, N=256,  K=256
// val[b] = key[b] @ mem[b]^T : M=2048,  N=1024, K=256, batch=8

#define BM 128
#define BN 128
#define BK 32
#define LDSS 36            // row stride (words); 36r mod 32 = 4r -> 8 distinct banks, LDSM conflict-free
#define TW (BM * LDSS)     // 4608 words per (A or B) tile
#define STW (2 * TW)       // 9216 words per stage (A+B)
#define NSTAGE 2
#define SMEM_BYTES (NSTAGE * STW * 4)   // 73728

__device__ __forceinline__ uint32_t f2tf32(float f) {
    uint32_t r;
    asm("cvt.rna.tf32.f32 %0, %1;" : "=r"(r) : "f"(f));
    return r;
}
__device__ __forceinline__ uint32_t cvtbits(uint32_t x) {
    return f2tf32(__uint_as_float(x));
}

__device__ __forceinline__ uint32_t s2u(const void* p) {
    uint32_t a;
    asm("{ .reg .u64 t; cvta.to.shared.u64 t, %1; cvt.u32.u64 %0, t; }" : "=r"(a) : "l"(p));
    return a;
}

__device__ __forceinline__ void cp16(uint32_t dst, const void* src) {
    asm volatile("cp.async.ca.shared.global [%0], [%1], 16;" :: "r"(dst), "l"(src));
}

__device__ __forceinline__ void ldsm4(uint32_t& r0, uint32_t& r1, uint32_t& r2, uint32_t& r3,
                                      uint32_t addr) {
    asm volatile("ldmatrix.sync.aligned.m8n8.x4.shared.b16 {%0,%1,%2,%3}, [%4];"
                 : "=r"(r0), "=r"(r1), "=r"(r2), "=r"(r3) : "r"(addr));
}

template<bool RELU>
__global__ __launch_bounds__(256, 2)
void tf32_mma_nt(const float* __restrict__ A, const float* __restrict__ B,
                 float* __restrict__ C, int K, int N,
                 long sA, long sB, long sC)
{
    extern __shared__ uint32_t smem[];

    const int tid  = threadIdx.x;
    const int lane = tid & 31;
    const int warp = tid >> 5;
    const int wm   = warp >> 1;    // 0..3 -> M offset wm*32
    const int wn   = warp & 1;     // 0..1 -> N offset wn*64

    A += (long)blockIdx.z * sA + (long)blockIdx.y * BM * K;
    B += (long)blockIdx.z * sB + (long)blockIdx.x * BN * K;
    C += (long)blockIdx.z * sC;

    // cp.async mapping: per tile 128 rows x 32 cols = 1024 float4; 256 thr -> 4 each.
    // thread -> row gr (0..127), half gh in {0,16} words; 4 x 16B at gh+{0,4,8,12}.
    const int gr = tid >> 1;
    const int gh = (tid & 1) * 16;

    const uint32_t sbase = s2u(smem);
    const uint32_t dstA = (uint32_t)(gr * LDSS + gh) * 4u;
    const uint32_t dstB = dstA + (uint32_t)TW * 4u;
    const float* gA = A + (long)gr * K + gh;
    const float* gB = B + (long)gr * K + gh;

    // LDSM lane address bases (byte offsets within a tile)
    const int la_rowA = wm * 32 + ((lane >> 3) & 1) * 8 + (lane & 7);
    const int la_colA = (lane >> 4) * 4;
    const uint32_t aBase = (uint32_t)(la_rowA * LDSS + la_colA) * 4u;
    const int la_rowB = wn * 64 + (lane >> 4) * 8 + (lane & 7);
    const int la_colB = ((lane >> 3) & 1) * 4;
    const uint32_t bBase = (uint32_t)(la_rowB * LDSS + la_colB) * 4u + (uint32_t)TW * 4u;

    const int nchunks = K / BK;    // 8

    // prologue: issue stages 0 and 1
    #pragma unroll
    for (int s = 0; s < NSTAGE; s++) {
        const uint32_t st = sbase + (uint32_t)(s * STW) * 4u;
        #pragma unroll
        for (int j = 0; j < 4; j++) {
            cp16(st + dstA + (uint32_t)(j * 16), gA + s * BK + j * 4);
            cp16(st + dstB + (uint32_t)(j * 16), gB + s * BK + j * 4);
        }
        asm volatile("cp.async.commit_group;" ::: "memory");
    }

    float acc[2][8][4];
    #pragma unroll
    for (int mi = 0; mi < 2; mi++)
        #pragma unroll
        for (int ni = 0; ni < 8; ni++)
            #pragma unroll
            for (int j = 0; j < 4; j++)
                acc[mi][ni][j] = 0.0f;

    #pragma unroll 1
    for (int kc = 0; kc < nchunks; kc++) {
        // stage kc must be complete (at most 1 newer group still in flight)
        asm volatile("cp.async.wait_group 1;" ::: "memory");
        __syncthreads();

        const uint32_t stg = sbase + (uint32_t)((kc & 1) * STW) * 4u;

        #pragma unroll
        for (int ks = 0; ks < 4; ks++) {
            const uint32_t kByte = (uint32_t)(ks * 8) * 4u;
            uint32_t af[2][4], bf[8][2];
            #pragma unroll
            for (int mi = 0; mi < 2; mi++)
                ldsm4(af[mi][0], af[mi][1], af[mi][2], af[mi][3],
                      stg + aBase + (uint32_t)(mi * 16 * LDSS) * 4u + kByte);
            #pragma unroll
            for (int j = 0; j < 4; j++)
                ldsm4(bf[2 * j][0], bf[2 * j][1], bf[2 * j + 1][0], bf[2 * j + 1][1],
                      stg + bBase + (uint32_t)(j * 16 * LDSS) * 4u + kByte);

            #pragma unroll
            for (int mi = 0; mi < 2; mi++)
                #pragma unroll
                for (int j = 0; j < 4; j++)
                    af[mi][j] = cvtbits(af[mi][j]);
            #pragma unroll
            for (int ni = 0; ni < 8; ni++) {
                bf[ni][0] = cvtbits(bf[ni][0]);
                bf[ni][1] = cvtbits(bf[ni][1]);
            }

            #pragma unroll
            for (int mi = 0; mi < 2; mi++)
                #pragma unroll
                for (int ni = 0; ni < 8; ni++)
                    asm volatile(
                        "mma.sync.aligned.m16n8k8.row.col.f32.tf32.tf32.f32 "
                        "{%0,%1,%2,%3}, {%4,%5,%6,%7}, {%8,%9}, {%0,%1,%2,%3};"
                        : "+f"(acc[mi][ni][0]), "+f"(acc[mi][ni][1]),
                          "+f"(acc[mi][ni][2]), "+f"(acc[mi][ni][3])
                        : "r"(af[mi][0]), "r"(af[mi][1]), "r"(af[mi][2]), "r"(af[mi][3]),
                          "r"(bf[ni][0]), "r"(bf[ni][1]));
        }

        // all warps done reading this stage; refill it with chunk kc+2
        __syncthreads();
        if (kc + NSTAGE < nchunks) {
            const int s = kc + NSTAGE;
            #pragma unroll
            for (int j = 0; j < 4; j++) {
                cp16(stg + dstA + (uint32_t)(j * 16), gA + s * BK + j * 4);
                cp16(stg + dstB + (uint32_t)(j * 16), gB + s * BK + j * 4);
            }
        }
        asm volatile("cp.async.commit_group;" ::: "memory");
    }

    // Epilogue: c0,c1 at (row, col), c2,c3 at (row+8, col); col = 2*(lane&3)
    #pragma unroll
    for (int mi = 0; mi < 2; mi++) {
        const long row = (long)blockIdx.y * BM + wm * 32 + mi * 16 + (lane >> 2);
        #pragma unroll
        for (int ni = 0; ni < 8; ni++) {
            const long col = (long)blockIdx.x * BN + wn * 64 + ni * 8 + (lane & 3) * 2;
            float2 v0 = make_float2(acc[mi][ni][0], acc[mi][ni][1]);
            float2 v1 = make_float2(acc[mi][ni][2], acc[mi][ni][3]);
            if (RELU) {
                v0.x = fmaxf(v0.x, 0.0f); v0.y = fmaxf(v0.y, 0.0f);
                v1.x = fmaxf(v1.x, 0.0f); v1.y = fmaxf(v1.y, 0.0f);
            }
            *(float2*)(C + row * N + col)       = v0;
            *(float2*)(C + (row + 8) * N + col) = v1;
        }
    }
}

extern "C" void kernel_launch(void* const* d_in, const int* in_sizes, int n_in,
                              void* d_out, int out_size)
{
    (void)in_sizes; (void)n_in; (void)out_size;

    const float* x   = (const float*)d_in[0];  // (8,2048,256)
    const float* mem = (const float*)d_in[1];  // (8,1024,256)
    const float* W   = (const float*)d_in[2];  // (256,256)

    float* key = (float*)d_out;                      // 16384*256
    float* val = (float*)d_out + (long)16384 * 256;  // 16384*1024

    static int configured = 0;
    if (!configured) {
        cudaFuncSetAttribute(tf32_mma_nt<true>,
                             cudaFuncAttributeMaxDynamicSharedMemorySize, SMEM_BYTES);
        cudaFuncSetAttribute(tf32_mma_nt<false>,
                             cudaFuncAttributeMaxDynamicSharedMemorySize, SMEM_BYTES);
        configured = 1;
    }

    // GEMM 1: key = relu(x @ W^T)  M=16384 N=256 K=256 -> grid (2,128)
    {
        dim3 grid(256 / BN, 16384 / BM, 1);
        tf32_mma_nt<true><<<grid, 256, SMEM_BYTES>>>(x, W, key, 256, 256, 0, 0, 0);
    }
    // GEMM 2: val[b] = key[b] @ mem[b]^T  M=2048 N=1024 K=256, batch 8 -> grid (8,16,8)
    {
        dim3 grid(1024 / BN, 2048 / BM, 8);
        tf32_mma_nt<false><<<grid, 256, SMEM_BYTES>>>(
            key, mem, val, 256, 1024,
            (long)2048 * 256, (long)1024 * 256, (long)2048 * 1024);
    }
}

// round 12
// speedup vs baseline: 1.0325x; 1.0325x over previous
#include <cuda_runtime.h>
#include <cstdint>

// ReadingLayerReLU via mma.sync.m16n8k8 tf32 + ldmatrix + TMA bulk fills.
// Fills go global->shared via cp.async.bulk (TMA engine, mbarrier complete_tx),
// bypassing the saturated L1tex/LSU path. 128x128 block tile, 256 threads
// (8 warps, 4x2, 32x64 warp tile), BK=32, 2-stage, 2 CTAs/SM.
// key = relu(x @ W^T)        : M=16384, N=256,  K=256
// val[b] = key[b] @ mem[b]^T : M=2048,  N=1024, K=256, batch=8

#define BM 128
#define BN 128
#define BK 32
#define LDSS 36            // row stride (words) = 144 B: 16B-aligned, LDSM conflict-free
#define TW (BM * LDSS)     // 4608 words per tile
#define STW (2 * TW)       // words per stage (A+B)
#define NSTAGE 2
#define SMEM_BYTES (NSTAGE * STW * 4)   // 73728
#define STAGE_TX (2 * BM * BK * 4)      // 32768 bytes filled per stage

__device__ __forceinline__ uint32_t f2tf32(float f) {
    uint32_t r;
    asm("cvt.rna.tf32.f32 %0, %1;" : "=r"(r) : "f"(f));
    return r;
}
__device__ __forceinline__ uint32_t cvtbits(uint32_t x) {
    return f2tf32(__uint_as_float(x));
}

__device__ __forceinline__ uint32_t s2u(const void* p) {
    uint32_t a;
    asm("{ .reg .u64 t; cvta.to.shared.u64 t, %1; cvt.u32.u64 %0, t; }" : "=r"(a) : "l"(p));
    return a;
}

__device__ __forceinline__ void bulk128(uint32_t dst, const void* src, uint32_t mbar) {
    asm volatile(
        "cp.async.bulk.shared::cluster.global.mbarrier::complete_tx::bytes "
        "[%0], [%1], 128, [%2];"
        :: "r"(dst), "l"(src), "r"(mbar) : "memory");
}

__device__ __forceinline__ void ldsm4(uint32_t& r0, uint32_t& r1, uint32_t& r2, uint32_t& r3,
                                      uint32_t addr) {
    asm volatile("ldmatrix.sync.aligned.m8n8.x4.shared.b16 {%0,%1,%2,%3}, [%4];"
                 : "=r"(r0), "=r"(r1), "=r"(r2), "=r"(r3) : "r"(addr));
}

#define MBAR_WAIT(a, par) do {                                                    \
    uint32_t _m = (a), _p = (par), _d;                                            \
    asm volatile("{\n\t.reg .pred p;\n\t"                                         \
        "mbarrier.try_wait.parity.acquire.cta.shared::cta.b64 p, [%1], %2;\n\t"   \
        "selp.b32 %0, 1, 0, p;\n\t}"                                              \
        : "=r"(_d) : "r"(_m), "r"(_p) : "memory");                                \
    if (!_d) {                                                                    \
        asm volatile("{\n\t.reg .pred P1;\n\t"                                    \
        "WL_%=:\n\t"                                                              \
        "mbarrier.try_wait.parity.acquire.cta.shared::cta.b64 P1, [%0], %1, 0x989680;\n\t" \
        "@P1 bra.uni WD_%=;\n\t"                                                  \
        "bra.uni WL_%=;\n\t"                                                      \
        "WD_%=:\n\t}" :: "r"(_m), "r"(_p) : "memory");                            \
    }                                                                             \
} while (0)

template<bool RELU>
__global__ __launch_bounds__(256, 2)
void tf32_mma_nt(const float* __restrict__ A, const float* __restrict__ B,
                 float* __restrict__ C, int K, int N,
                 long sA, long sB, long sC)
{
    extern __shared__ uint32_t smem[];
    __shared__ __align__(8) unsigned long long mbar[NSTAGE];

    const int tid  = threadIdx.x;
    const int lane = tid & 31;
    const int warp = tid >> 5;
    const int wm   = warp >> 1;    // 0..3 -> M offset wm*32
    const int wn   = warp & 1;     // 0..1 -> N offset wn*64

    A += (long)blockIdx.z * sA + (long)blockIdx.y * BM * K;
    B += (long)blockIdx.z * sB + (long)blockIdx.x * BN * K;
    C += (long)blockIdx.z * sC;

    const uint32_t sbase = s2u(smem);
    const uint32_t mb0 = s2u(&mbar[0]);
    const uint32_t mb1 = s2u(&mbar[1]);

    // TMA fill mapping: thread t<128 copies A row t; t>=128 copies B row t-128.
    // One 128-B bulk copy per thread per stage (BK=32 floats).
    const int  crow   = tid & 127;
    const bool isB    = tid >= 128;
    const float* gsrc = (isB ? B : A) + (long)crow * K;
    const uint32_t cdst = (uint32_t)((isB ? TW : 0) + crow * LDSS) * 4u;

    // LDSM lane address bases (byte offsets within a tile)
    const int la_rowA = wm * 32 + ((lane >> 3) & 1) * 8 + (lane & 7);
    const int la_colA = (lane >> 4) * 4;
    const uint32_t aBase = (uint32_t)(la_rowA * LDSS + la_colA) * 4u;
    const int la_rowB = wn * 64 + (lane >> 4) * 8 + (lane & 7);
    const int la_colB = ((lane >> 3) & 1) * 4;
    const uint32_t bBase = (uint32_t)(la_rowB * LDSS + la_colB) * 4u + (uint32_t)TW * 4u;

    const int nchunks = K / BK;    // 8

    // init barriers
    if (tid == 0) {
        asm volatile("mbarrier.init.shared.b64 [%0], 1;" :: "r"(mb0) : "memory");
        asm volatile("mbarrier.init.shared.b64 [%0], 1;" :: "r"(mb1) : "memory");
    }
    __syncthreads();

    // prologue: fill stages 0 (chunk 0) and 1 (chunk 1)
    if (tid == 0) {
        asm volatile("mbarrier.arrive.expect_tx.shared.b64 _, [%0], %1;"
                     :: "r"(mb0), "r"((uint32_t)STAGE_TX) : "memory");
        asm volatile("mbarrier.arrive.expect_tx.shared.b64 _, [%0], %1;"
                     :: "r"(mb1), "r"((uint32_t)STAGE_TX) : "memory");
    }
    bulk128(sbase + cdst, gsrc, mb0);
    bulk128(sbase + (uint32_t)STW * 4u + cdst, gsrc + BK, mb1);

    float acc[2][8][4];
    #pragma unroll
    for (int mi = 0; mi < 2; mi++)
        #pragma unroll
        for (int ni = 0; ni < 8; ni++)
            #pragma unroll
            for (int j = 0; j < 4; j++)
                acc[mi][ni][j] = 0.0f;

    int ph0 = 0, ph1 = 0;

    #pragma unroll 1
    for (int kc = 0; kc < nchunks; kc++) {
        const int buf = kc & 1;
        const uint32_t mb = buf ? mb1 : mb0;
        if (buf == 0) { MBAR_WAIT(mb, ph0); ph0 ^= 1; }
        else          { MBAR_WAIT(mb, ph1); ph1 ^= 1; }

        const uint32_t stg = sbase + (uint32_t)(buf * STW) * 4u;

        #pragma unroll
        for (int ks = 0; ks < 4; ks++) {
            const uint32_t kByte = (uint32_t)(ks * 8) * 4u;
            uint32_t af[2][4], bf[8][2];
            #pragma unroll
            for (int mi = 0; mi < 2; mi++)
                ldsm4(af[mi][0], af[mi][1], af[mi][2], af[mi][3],
                      stg + aBase + (uint32_t)(mi * 16 * LDSS) * 4u + kByte);
            #pragma unroll
            for (int j = 0; j < 4; j++)
                ldsm4(bf[2 * j][0], bf[2 * j][1], bf[2 * j + 1][0], bf[2 * j + 1][1],
                      stg + bBase + (uint32_t)(j * 16 * LDSS) * 4u + kByte);

            #pragma unroll
            for (int mi = 0; mi < 2; mi++)
                #pragma unroll
                for (int j = 0; j < 4; j++)
                    af[mi][j] = cvtbits(af[mi][j]);
            #pragma unroll
            for (int ni = 0; ni < 8; ni++) {
                bf[ni][0] = cvtbits(bf[ni][0]);
                bf[ni][1] = cvtbits(bf[ni][1]);
            }

            #pragma unroll
            for (int mi = 0; mi < 2; mi++)
                #pragma unroll
                for (int ni = 0; ni < 8; ni++)
                    asm volatile(
                        "mma.sync.aligned.m16n8k8.row.col.f32.tf32.tf32.f32 "
                        "{%0,%1,%2,%3}, {%4,%5,%6,%7}, {%8,%9}, {%0,%1,%2,%3};"
                        : "+f"(acc[mi][ni][0]), "+f"(acc[mi][ni][1]),
                          "+f"(acc[mi][ni][2]), "+f"(acc[mi][ni][3])
                        : "r"(af[mi][0]), "r"(af[mi][1]), "r"(af[mi][2]), "r"(af[mi][3]),
                          "r"(bf[ni][0]), "r"(bf[ni][1]));
        }

        // all warps finished reading this stage; refill with chunk kc+2
        __syncthreads();
        if (kc + NSTAGE < nchunks) {
            if (tid == 0)
                asm volatile("mbarrier.arrive.expect_tx.shared.b64 _, [%0], %1;"
                             :: "r"(mb), "r"((uint32_t)STAGE_TX) : "memory");
            bulk128(stg + cdst, gsrc + (kc + NSTAGE) * BK, mb);
        }
    }

    // Epilogue: c0,c1 at (row, col), c2,c3 at (row+8, col); col = 2*(lane&3)
    #pragma unroll
    for (int mi = 0; mi < 2; mi++) {
        const long row = (long)blockIdx.y * BM + wm * 32 + mi * 16 + (lane >> 2);
        #pragma unroll
        for (int ni = 0; ni < 8; ni++) {
            const long col = (long)blockIdx.x * BN + wn * 64 + ni * 8 + (lane & 3) * 2;
            float2 v0 = make_float2(acc[mi][ni][0], acc[mi][ni][1]);
            float2 v1 = make_float2(acc[mi][ni][2], acc[mi][ni][3]);
            if (RELU) {
                v0.x = fmaxf(v0.x, 0.0f); v0.y = fmaxf(v0.y, 0.0f);
                v1.x = fmaxf(v1.x, 0.0f); v1.y = fmaxf(v1.y, 0.0f);
            }
            *(float2*)(C + row * N + col)       = v0;
            *(float2*)(C + (row + 8) * N + col) = v1;
        }
    }
}

extern "C" void kernel_launch(void* const* d_in, const int* in_sizes, int n_in,
                              void* d_out, int out_size)
{
    (void)in_sizes; (void)n_in; (void)out_size;

    const float* x   = (const float*)d_in[0];  // (8,2048,256)
    const float* mem = (const float*)d_in[1];  // (8,1024,256)
    const float* W   = (const float*)d_in[2];  // (256,256)

    float* key = (float*)d_out;                      // 16384*256
    float* val = (float*)d_out + (long)16384 * 256;  // 16384*1024

    static int configured = 0;
    if (!configured) {
        cudaFuncSetAttribute(tf32_mma_nt<true>,
                             cudaFuncAttributeMaxDynamicSharedMemorySize, SMEM_BYTES);
        cudaFuncSetAttribute(tf32_mma_nt<false>,
                             cudaFuncAttributeMaxDynamicSharedMemorySize, SMEM_BYTES);
        configured = 1;
    }

    // GEMM 1: key = relu(x @ W^T)  M=16384 N=256 K=256 -> grid (2,128)
    {
        dim3 grid(256 / BN, 16384 / BM, 1);
        tf32_mma_nt<true><<<grid, 256, SMEM_BYTES>>>(x, W, key, 256, 256, 0, 0, 0);
    }
    // GEMM 2: val[b] = key[b] @ mem[b]^T  M=2048 N=1024 K=256, batch 8 -> grid (8,16,8)
    {
        dim3 grid(1024 / BN, 2048 / BM, 8);
        tf32_mma_nt<false><<<grid, 256, SMEM_BYTES>>>(
            key, mem, val, 256, 1024,
            (long)2048 * 256, (long)1024 * 256, (long)2048 * 1024);
    }
}